// round 2
// baseline (speedup 1.0000x reference)
#include <cuda_runtime.h>
#include <cuda_bf16.h>

// WeightedEmbeddingBag: score[b,m,:] = sum_{n=start..end-1} emb[input[b,n],:] * psw[b,n]
//   end_m   = offsets[b,m] + 1
//   start_m = (m==0) ? 0 : offsets[b,m-1] + 1      (offsets sorted -> disjoint segments)
//
// Inputs (metadata order): input int32 [B,N]  (JAX default x64-disabled: "int64" -> int32),
//                          per_sample_weights f32 [B,N],
//                          offsets int32 [B,M], emb_weight f32 [VOCAB,D]
// Output: f32 [B, M, D]

#define BB 4096
#define NN 200
#define MM 26
#define DD 128
#define D4 (DD / 4)   // 32 float4 per row -> one lane each

__global__ __launch_bounds__(256, 8)
void weighted_bag_kernel(const int* __restrict__ input,
                         const float* __restrict__ psw,
                         const int* __restrict__ offsets,
                         const float4* __restrict__ emb4,   // [VOCAB, D4]
                         float4* __restrict__ out4)         // [B, M, D4]
{
    const int warp = (blockIdx.x * blockDim.x + threadIdx.x) >> 5;
    const int lane = threadIdx.x & 31;
    if (warp >= BB) return;
    const int b = warp;

    const int*   __restrict__ offs = offsets + b * MM;
    const int*   __restrict__ inp  = input   + b * NN;
    const float* __restrict__ wrow = psw     + b * NN;
    float4*      __restrict__ orow = out4    + (long long)b * (MM * D4);

    int m   = 0;
    int end = offs[0] + 1;             // end of current bag (exclusive row index)
    const int last = offs[MM - 1] + 1; // total rows consumed for this batch

    float ax = 0.f, ay = 0.f, az = 0.f, aw = 0.f;

    for (int base = 0; base < last; base += 32) {
        // coalesced prefetch of up to 32 (index, weight) pairs
        const int n_l = base + lane;
        int   my_idx = 0;
        float my_w   = 0.f;
        if (n_l < last) {
            my_idx = inp[n_l];
            my_w   = wrow[n_l];
        }
        const int cnt = min(32, last - base);

        #pragma unroll 4
        for (int j = 0; j < cnt; ++j) {
            const int   idx = __shfl_sync(0xffffffffu, my_idx, j);
            const float w   = __shfl_sync(0xffffffffu, my_w,   j);

            const float4 v = __ldg(&emb4[(long long)idx * D4 + lane]);  // 512B coalesced row
            ax = fmaf(w, v.x, ax);
            ay = fmaf(w, v.y, ay);
            az = fmaf(w, v.z, az);
            aw = fmaf(w, v.w, aw);

            const int np1 = base + j + 1;
            // flush all bags that end here (duplicate offsets -> empty bags -> zeros)
            while (m < MM && np1 == end) {
                float4 o; o.x = ax; o.y = ay; o.z = az; o.w = aw;
                orow[m * D4 + lane] = o;
                ax = ay = az = aw = 0.f;
                ++m;
                end = (m < MM) ? offs[m] + 1 : 0x7fffffff;
            }
        }
    }
    // by construction, the last bag's end == last, so all MM bags get written
}

extern "C" void kernel_launch(void* const* d_in, const int* in_sizes, int n_in,
                              void* d_out, int out_size)
{
    const int*   input   = (const int*)  d_in[0];
    const float* psw     = (const float*)d_in[1];
    const int*   offsets = (const int*)  d_in[2];
    const float4* emb4   = (const float4*)d_in[3];
    float4*      out4    = (float4*)d_out;

    // 4096 batches, one warp each; 256 threads = 8 warps/block
    const int threads = 256;
    const int blocks  = (BB * 32 + threads - 1) / threads;  // 512
    weighted_bag_kernel<<<blocks, threads>>>(input, psw, offsets, emb4, out4);
}

// round 4
// speedup vs baseline: 1.1350x; 1.1350x over previous
#include <cuda_runtime.h>
#include <cuda_bf16.h>

// WeightedEmbeddingBag: score[b,m,:] = sum_{n=start_m..end_m-1} emb[input[b,n],:] * psw[b,n]
//   end_m = offsets[b,m]+1, start_m = (m==0) ? 0 : offsets[b,m-1]+1 (offsets sorted)
//
// 4 warps per batch, each warp owns a contiguous range of bags (disjoint row
// segments), LDG.128 row gathers, shfl-broadcast prefetched indices/weights.
// Empty bags (duplicate offsets): leading ones flushed as zeros BEFORE the row
// loop (R3 bug), mid-stream ones via the while-chain, trailing via the tail loop.
//
// Inputs: input int32 [B,N], per_sample_weights f32 [B,N],
//         offsets int32 [B,M], emb_weight f32 [VOCAB,D]. Output f32 [B,M,D].

#define BB 4096
#define NN 200
#define MM 26
#define DD 128
#define D4 (DD / 4)     // 32 float4 per row -> one lane each
#define PARTS 4         // warps per batch

__global__ __launch_bounds__(256)
void weighted_bag_kernel(const int* __restrict__ input,
                         const float* __restrict__ psw,
                         const int* __restrict__ offsets,
                         const float4* __restrict__ emb4,   // [VOCAB, D4]
                         float4* __restrict__ out4)         // [B, M, D4]
{
    const int gw   = (blockIdx.x * blockDim.x + threadIdx.x) >> 5;
    const int lane = threadIdx.x & 31;
    if (gw >= BB * PARTS) return;
    const int b = gw / PARTS;
    const int p = gw % PARTS;

    const int m_lo = (p * MM) / PARTS;           // 0,6,13,19
    const int m_hi = ((p + 1) * MM) / PARTS;     // 6,13,19,26

    const int*   __restrict__ offs = offsets + b * MM;
    const int*   __restrict__ inp  = input   + b * NN;
    const float* __restrict__ wrow = psw     + b * NN;
    float4*      __restrict__ orow = out4    + (long long)b * (MM * D4);

    const int start = (m_lo == 0) ? 0 : offs[m_lo - 1] + 1;  // first row of this part
    const int last  = offs[m_hi - 1] + 1;                    // one past last row

    int m = m_lo;

    // Flush leading EMPTY bags (end == start). The row loop can only flush bags
    // with end > start since np1 starts at start+1.
    while (m < m_hi && offs[m] + 1 == start) {
        float4 z; z.x = z.y = z.z = z.w = 0.f;
        orow[m * D4 + lane] = z;
        ++m;
    }
    int end = (m < m_hi) ? offs[m] + 1 : 0x7fffffff;

    float ax = 0.f, ay = 0.f, az = 0.f, aw = 0.f;

    for (int base = start; base < last; base += 32) {
        // coalesced prefetch of up to 32 (index, weight) pairs
        const int n_l = base + lane;
        int   my_idx = 0;
        float my_w   = 0.f;
        if (n_l < last) {
            my_idx = inp[n_l];
            my_w   = wrow[n_l];
        }
        const int cnt = min(32, last - base);

        #pragma unroll 4
        for (int j = 0; j < cnt; ++j) {
            const int   idx = __shfl_sync(0xffffffffu, my_idx, j);
            const float w   = __shfl_sync(0xffffffffu, my_w,   j);

            const float4 v = __ldg(&emb4[(long long)idx * D4 + lane]);  // 512B row gather
            ax = fmaf(w, v.x, ax);
            ay = fmaf(w, v.y, ay);
            az = fmaf(w, v.z, az);
            aw = fmaf(w, v.w, aw);

            const int np1 = base + j + 1;
            // flush every bag ending at this row (duplicates -> empty bags -> zeros)
            while (m < m_hi && np1 == end) {
                float4 o; o.x = ax; o.y = ay; o.z = az; o.w = aw;
                orow[m * D4 + lane] = o;
                ax = ay = az = aw = 0.f;
                ++m;
                end = (m < m_hi) ? offs[m] + 1 : 0x7fffffff;
            }
        }
    }

    // Any remaining bags are empty (possible only when start == last): zeros.
    while (m < m_hi) {
        float4 z; z.x = z.y = z.z = z.w = 0.f;
        orow[m * D4 + lane] = z;
        ++m;
    }
}

extern "C" void kernel_launch(void* const* d_in, const int* in_sizes, int n_in,
                              void* d_out, int out_size)
{
    const int*    input   = (const int*)   d_in[0];
    const float*  psw     = (const float*) d_in[1];
    const int*    offsets = (const int*)   d_in[2];
    const float4* emb4    = (const float4*)d_in[3];
    float4*       out4    = (float4*)d_out;

    // 4096 batches x 4 warps each; 256 threads = 8 warps/block -> 2048 blocks
    const int threads = 256;
    const int blocks  = (BB * PARTS * 32 + threads - 1) / threads;
    weighted_bag_kernel<<<blocks, threads>>>(input, psw, offsets, emb4, out4);
}

// round 5
// speedup vs baseline: 1.2700x; 1.1190x over previous
#include <cuda_runtime.h>
#include <cuda_bf16.h>

// WeightedEmbeddingBag: score[b,m,:] = sum_{n=start_m..end_m-1} emb[input[b,n],:] * psw[b,n]
//   end_m = offsets[b,m]+1, start_m = (m==0) ? 0 : offsets[b,m-1]+1 (offsets sorted)
//
// R5: ONE WARP PER BAG. Bags partition the row range, so gather traffic is
// unchanged, but the inner loop has zero bag-boundary logic: prefetch 32
// (idx,w) pairs coalesced, shfl-broadcast, LDG.128 row gather, FMA. One store
// per warp. Empty bags (duplicate offsets) skip the loop and store zeros.
//
// Inputs: input int32 [B,N], per_sample_weights f32 [B,N],
//         offsets int32 [B,M], emb_weight f32 [VOCAB,D]. Output f32 [B,M,D].

#define BB 4096
#define NN 200
#define MM 26
#define DD 128
#define D4 (DD / 4)   // 32 float4 per row -> one lane each

__global__ __launch_bounds__(256, 8)
void weighted_bag_kernel(const int* __restrict__ input,
                         const float* __restrict__ psw,
                         const int* __restrict__ offsets,
                         const float4* __restrict__ emb4,   // [VOCAB, D4]
                         float4* __restrict__ out4)         // [B, M, D4]
{
    const int gw   = (blockIdx.x * blockDim.x + threadIdx.x) >> 5;
    const int lane = threadIdx.x & 31;
    if (gw >= BB * MM) return;
    const int b = gw / MM;
    const int m = gw - b * MM;

    const int* __restrict__ offs = offsets + b * MM;
    const int end   = __ldg(&offs[m]) + 1;
    const int start = (m == 0) ? 0 : __ldg(&offs[m - 1]) + 1;

    const int*   __restrict__ inp  = input + b * NN;
    const float* __restrict__ wrow = psw   + b * NN;

    float ax = 0.f, ay = 0.f, az = 0.f, aw = 0.f;

    for (int base = start; base < end; base += 32) {
        // coalesced prefetch of up to 32 (index, weight) pairs
        const int n_l = base + lane;
        int   my_idx = 0;
        float my_w   = 0.f;
        if (n_l < end) {
            my_idx = __ldg(&inp[n_l]);
            my_w   = __ldg(&wrow[n_l]);
        }
        const int cnt = min(32, end - base);

        #pragma unroll 4
        for (int j = 0; j < cnt; ++j) {
            const int   idx = __shfl_sync(0xffffffffu, my_idx, j);
            const float w   = __shfl_sync(0xffffffffu, my_w,   j);

            const float4 v = __ldg(&emb4[(long long)idx * D4 + lane]);  // 512B row gather
            ax = fmaf(w, v.x, ax);
            ay = fmaf(w, v.y, ay);
            az = fmaf(w, v.z, az);
            aw = fmaf(w, v.w, aw);
        }
    }

    float4 o; o.x = ax; o.y = ay; o.z = az; o.w = aw;
    out4[((long long)b * MM + m) * D4 + lane] = o;   // empty bag -> zeros
}

extern "C" void kernel_launch(void* const* d_in, const int* in_sizes, int n_in,
                              void* d_out, int out_size)
{
    const int*    input   = (const int*)   d_in[0];
    const float*  psw     = (const float*) d_in[1];
    const int*    offsets = (const int*)   d_in[2];
    const float4* emb4    = (const float4*)d_in[3];
    float4*       out4    = (float4*)d_out;

    // one warp per (batch, bag): 4096*26 = 106496 warps; 8 warps/block
    const int threads = 256;
    const long long warps = (long long)BB * MM;
    const int blocks = (int)((warps * 32 + threads - 1) / threads);
    weighted_bag_kernel<<<blocks, threads>>>(input, psw, offsets, emb4, out4);
}